// round 10
// baseline (speedup 1.0000x reference)
#include <cuda_runtime.h>
#include <cstdint>

// P=50000, H=W=28, CARD=50
// Inputs: p[50000] f32, I[784*50000] f32, J[784*50000] f32,
//         inds1[100*2] i32, inds2[100*2] i32
// Output: 200 f32

#define P_DIM    50000
#define W_IMG    28
#define N_OUT    200
#define ROW_F4   (P_DIM / 4)          // 12500 float4 per row
#define RPB      4                    // rows (outputs) per block
#define NGROUPS  (N_OUT / RPB)        // 50
#define SPLIT    25                   // 12500 / 25 = 500 f4 per chunk (exact)
#define LEN_F4   (ROW_F4 / SPLIT)     // 500
#define STAGE_F4 250                  // 2 exact stages, threads tid<250 active
#define NSTAGE   2
#define NBLOCKS  (NGROUPS * SPLIT)    // 1250
#define NTHREADS 256
#define NSEG     5                    // p + 4 rows

__device__ float g_partial[N_OUT * SPLIT];
__device__ unsigned int g_done = 0;

__device__ __forceinline__ uint32_t smem_u32(const void* p_) {
    uint32_t a;
    asm("{ .reg .u64 t; cvta.to.shared.u64 t, %1; cvt.u32.u64 %0, t; }"
        : "=r"(a) : "l"(p_));
    return a;
}

__device__ __forceinline__ void cp16(uint32_t dst, const void* src) {
    asm volatile("cp.async.cg.shared.global [%0], [%1], 16;"
                 :: "r"(dst), "l"(src) : "memory");
}

__device__ __forceinline__ float block_reduce(float v, float* ws) {
    #pragma unroll
    for (int off = 16; off > 0; off >>= 1)
        v += __shfl_down_sync(0xffffffffu, v, off);
    if ((threadIdx.x & 31) == 0) ws[threadIdx.x >> 5] = v;
    __syncthreads();
    float r = 0.0f;
    if (threadIdx.x < (NTHREADS / 32)) r = ws[threadIdx.x];
    if (threadIdx.x < 32) {
        #pragma unroll
        for (int off = (NTHREADS / 64); off > 0; off >>= 1)
            r += __shfl_down_sync(0xffu, r, off);
    }
    __syncthreads();
    return r;   // valid in thread 0
}

__global__ __launch_bounds__(NTHREADS)
void fused_cpasync_dot(const float* __restrict__ p,
                       const float* __restrict__ I,
                       const float* __restrict__ J,
                       const int*   __restrict__ inds1,
                       const int*   __restrict__ inds2,
                       float*       __restrict__ out) {
    // [stage][segment][slot] ; each thread touches only slot==tid
    __shared__ float4 sbuf[NSTAGE][NSEG][STAGE_F4];
    __shared__ float  ws[NTHREADS / 32];
    __shared__ bool   s_last;

    const int b   = blockIdx.x;
    const int g   = b / SPLIT;      // group -> outputs 4g..4g+3
    const int c   = b % SPLIT;      // chunk
    const int tid = threadIdx.x;

    const float* mat;
    const int*   inds;
    int jbase;
    if (g < NGROUPS / 2) { mat = I; inds = inds1; jbase = g * RPB; }
    else                 { mat = J; inds = inds2; jbase = g * RPB - 100; }

    const float4* seg_src[NSEG];
    seg_src[0] = reinterpret_cast<const float4*>(p);
    #pragma unroll
    for (int u = 0; u < RPB; u++) {
        int j  = jbase + u;
        int rr = inds[2 * j + 0];
        int cc = inds[2 * j + 1];
        seg_src[u + 1] = reinterpret_cast<const float4*>(mat) +
                         (size_t)(rr * W_IMG + cc) * ROW_F4;
    }

    const int start = c * LEN_F4;   // f4 offset of this chunk

    // ---- issue all 10 register-free async loads ----
    if (tid < STAGE_F4) {
        #pragma unroll
        for (int s = 0; s < NSTAGE; s++) {
            int i = start + s * STAGE_F4 + tid;
            #pragma unroll
            for (int e = 0; e < NSEG; e++)
                cp16(smem_u32(&sbuf[s][e][tid]), &seg_src[e][i]);
        }
    }
    asm volatile("cp.async.wait_all;" ::: "memory");

    // ---- consume own staged data (no barrier needed) ----
    float a0 = 0.f, a1 = 0.f, a2 = 0.f, a3 = 0.f;
    if (tid < STAGE_F4) {
        #pragma unroll
        for (int s = 0; s < NSTAGE; s++) {
            float4 q  = sbuf[s][0][tid];
            float4 v0 = sbuf[s][1][tid];
            float4 v1 = sbuf[s][2][tid];
            float4 v2 = sbuf[s][3][tid];
            float4 v3 = sbuf[s][4][tid];
            a0 += v0.x * q.x + v0.y * q.y + v0.z * q.z + v0.w * q.w;
            a1 += v1.x * q.x + v1.y * q.y + v1.z * q.z + v1.w * q.w;
            a2 += v2.x * q.x + v2.y * q.y + v2.z * q.z + v2.w * q.w;
            a3 += v3.x * q.x + v3.y * q.y + v3.z * q.z + v3.w * q.w;
        }
    }

    float t0 = block_reduce(a0, ws);
    float t1 = block_reduce(a1, ws);
    float t2 = block_reduce(a2, ws);
    float t3 = block_reduce(a3, ws);

    if (tid == 0) {
        int ob = g * RPB;
        g_partial[(ob + 0) * SPLIT + c] = t0;
        g_partial[(ob + 1) * SPLIT + c] = t1;
        g_partial[(ob + 2) * SPLIT + c] = t2;
        g_partial[(ob + 3) * SPLIT + c] = t3;
        __threadfence();
        unsigned int prev = atomicAdd(&g_done, 1u);
        s_last = (prev == NBLOCKS - 1);
    }
    __syncthreads();

    if (s_last) {
        int oo = tid;
        if (oo < N_OUT) {
            float s = 0.0f;
            #pragma unroll
            for (int k = 0; k < SPLIT; k++) s += g_partial[oo * SPLIT + k];
            out[oo] = s;
        }
        if (tid == 0) g_done = 0;   // reset for next graph replay
    }
}

extern "C" void kernel_launch(void* const* d_in, const int* in_sizes, int n_in,
                              void* d_out, int out_size) {
    const float* p     = (const float*)d_in[0];
    const float* I     = (const float*)d_in[1];
    const float* J     = (const float*)d_in[2];
    const int*   inds1 = (const int*)d_in[3];
    const int*   inds2 = (const int*)d_in[4];
    float* out = (float*)d_out;

    fused_cpasync_dot<<<NBLOCKS, NTHREADS>>>(p, I, J, inds1, inds2, out);
}

// round 11
// speedup vs baseline: 1.1400x; 1.1400x over previous
#include <cuda_runtime.h>
#include <cstdint>

// P=50000, H=W=28, CARD=50
// Inputs: p[50000] f32, I[784*50000] f32, J[784*50000] f32,
//         inds1[100*2] i32, inds2[100*2] i32
// Output: 200 f32

#define P_DIM    50000
#define W_IMG    28
#define N_OUT    200
#define ROW_F4   (P_DIM / 4)        // 12500 float4 per row
#define RPB      4                  // rows (outputs) per block
#define NGROUPS  (N_OUT / RPB)      // 50
#define SPLIT    12                 // K-chunks per group
#define NBLOCKS  (NGROUPS * SPLIT)  // 600
#define NTHREADS 256

__device__ float g_partial[N_OUT * SPLIT];
__device__ unsigned int g_done = 0;

__device__ __forceinline__ void l2_prefetch(const void* ptr) {
    asm volatile("prefetch.global.L2 [%0];" :: "l"(ptr));
}

__device__ __forceinline__ float block_reduce(float v, float* ws) {
    #pragma unroll
    for (int off = 16; off > 0; off >>= 1)
        v += __shfl_down_sync(0xffffffffu, v, off);
    if ((threadIdx.x & 31) == 0) ws[threadIdx.x >> 5] = v;
    __syncthreads();
    float r = 0.0f;
    if (threadIdx.x < (NTHREADS / 32)) r = ws[threadIdx.x];
    if (threadIdx.x < 32) {
        #pragma unroll
        for (int off = (NTHREADS / 64); off > 0; off >>= 1)
            r += __shfl_down_sync(0xffu, r, off);
    }
    __syncthreads();
    return r;   // valid in thread 0
}

__global__ __launch_bounds__(NTHREADS)
void fused_pf_dot(const float* __restrict__ p,
                  const float* __restrict__ I,
                  const float* __restrict__ J,
                  const int*   __restrict__ inds1,
                  const int*   __restrict__ inds2,
                  float*       __restrict__ out) {
    const int b   = blockIdx.x;
    const int g   = b / SPLIT;      // output group 0..49 -> outputs 4g..4g+3
    const int c   = b % SPLIT;      // K-chunk
    const int tid = threadIdx.x;

    const float* mat;
    const int*   inds;
    int jbase;
    if (g < NGROUPS / 2) { mat = I; inds = inds1; jbase = g * RPB; }
    else                 { mat = J; inds = inds2; jbase = g * RPB - 100; }

    const float4* r4[RPB];
    #pragma unroll
    for (int u = 0; u < RPB; u++) {
        int j  = jbase + u;
        int rr = inds[2 * j + 0];
        int cc = inds[2 * j + 1];
        r4[u] = reinterpret_cast<const float4*>(mat) +
                (size_t)(rr * W_IMG + cc) * ROW_F4;
    }
    const float4* p4 = reinterpret_cast<const float4*>(p);

    // chunk bounds in float4 units
    const int start = (c * ROW_F4) / SPLIT;
    const int end   = ((c + 1) * ROW_F4) / SPLIT;

    // ---- phase 0: fire-and-forget L2 prefetch of the whole chunk ----
    // one prefetch per 128B line (8 float4); 5 streams
    {
        const int line0 = start >> 3;                 // inclusive
        const int line1 = (end + 7) >> 3;             // exclusive
        const int nl    = line1 - line0;              // ~131 lines per stream
        for (int k = tid; k < nl; k += NTHREADS) {
            const char* off = (const char*)0 + (size_t)(line0 + k) * 128;
            l2_prefetch((const char*)p4 + (size_t)(line0 + k) * 128);
            #pragma unroll
            for (int u = 0; u < RPB; u++)
                l2_prefetch((const char*)r4[u] + (size_t)(line0 + k) * 128);
            (void)off;
        }
    }

    // ---- phase 1: demand loop (hits L2 once prefetches land) ----
    float a0 = 0.0f, a1 = 0.0f, a2 = 0.0f, a3 = 0.0f;
    #pragma unroll 2
    for (int i = start + tid; i < end; i += NTHREADS) {
        float4 q  = p4[i];
        float4 v0 = r4[0][i];
        float4 v1 = r4[1][i];
        float4 v2 = r4[2][i];
        float4 v3 = r4[3][i];
        a0 += v0.x * q.x + v0.y * q.y + v0.z * q.z + v0.w * q.w;
        a1 += v1.x * q.x + v1.y * q.y + v1.z * q.z + v1.w * q.w;
        a2 += v2.x * q.x + v2.y * q.y + v2.z * q.z + v2.w * q.w;
        a3 += v3.x * q.x + v3.y * q.y + v3.z * q.z + v3.w * q.w;
    }

    __shared__ float ws[NTHREADS / 32];
    __shared__ bool  s_last;

    float t0 = block_reduce(a0, ws);
    float t1 = block_reduce(a1, ws);
    float t2 = block_reduce(a2, ws);
    float t3 = block_reduce(a3, ws);

    if (tid == 0) {
        int ob = g * RPB;
        g_partial[(ob + 0) * SPLIT + c] = t0;
        g_partial[(ob + 1) * SPLIT + c] = t1;
        g_partial[(ob + 2) * SPLIT + c] = t2;
        g_partial[(ob + 3) * SPLIT + c] = t3;
        __threadfence();
        unsigned int prev = atomicAdd(&g_done, 1u);
        s_last = (prev == NBLOCKS - 1);
    }
    __syncthreads();

    if (s_last) {
        int oo = tid;
        if (oo < N_OUT) {
            float s = 0.0f;
            #pragma unroll
            for (int k = 0; k < SPLIT; k++) s += g_partial[oo * SPLIT + k];
            out[oo] = s;
        }
        if (tid == 0) g_done = 0;   // reset for next graph replay
    }
}

extern "C" void kernel_launch(void* const* d_in, const int* in_sizes, int n_in,
                              void* d_out, int out_size) {
    const float* p     = (const float*)d_in[0];
    const float* I     = (const float*)d_in[1];
    const float* J     = (const float*)d_in[2];
    const int*   inds1 = (const int*)d_in[3];
    const int*   inds2 = (const int*)d_in[4];
    float* out = (float*)d_out;

    fused_pf_dot<<<NBLOCKS, NTHREADS>>>(p, I, J, inds1, inds2, out);
}